// round 16
// baseline (speedup 1.0000x reference)
#include <cuda_runtime.h>
#include <cuda_fp16.h>
#include <cstdint>

#define T_STEPS 512
#define BATCH   2048
#define IN_DIM  12
#define E_DIM   15
#define H_DIM   20
#define XS      (BATCH * IN_DIM)
#define OS      (BATCH * 3)
#define TPAD    (T_STEPS + 4)         // prefetch pad

typedef unsigned long long u64;
typedef uint32_t u32;

// Scratch: x-gate pre-activations as half4 (i,f,g,o) = one u64 per (b,t,cell).
__device__ __align__(16) u64    g_xg[(size_t)BATCH * TPAD * H_DIM];
__device__ __align__(16) u64    g_wcx[4][H_DIM][6];
__device__ __align__(16) float4 g_bc4[H_DIM];

__device__ __forceinline__ u64 pack2(float x, float y) {
    u64 u; asm("mov.b64 %0, {%1, %2};" : "=l"(u) : "f"(x), "f"(y)); return u;
}
__device__ __forceinline__ void unpack2(float& x, float& y, u64 u) {
    asm("mov.b64 {%0, %1}, %2;" : "=f"(x), "=f"(y) : "l"(u));
}
__device__ __forceinline__ u64 pack2u(u32 lo, u32 hi) {
    u64 u; asm("mov.b64 %0, {%1, %2};" : "=l"(u) : "r"(lo), "r"(hi)); return u;
}
__device__ __forceinline__ void unpack2u(u32& lo, u32& hi, u64 u) {
    asm("mov.b64 {%0, %1}, %2;" : "=r"(lo), "=r"(hi) : "l"(u));
}
__device__ __forceinline__ void fma2(u64& d, u64 a, u64 b) {
    asm("fma.rn.f32x2 %0, %1, %2, %0;" : "+l"(d) : "l"(a), "l"(b));
}
__device__ __forceinline__ float hsum2(u64 u) {
    float x, y; unpack2(x, y, u); return x + y;
}
__device__ __forceinline__ float tanh_a(float x) {
    float y; asm("tanh.approx.f32 %0, %1;" : "=f"(y) : "f"(x)); return y;
}
__device__ __forceinline__ float sig_a(float x) {
    return fmaf(0.5f, tanh_a(0.5f * x), 0.5f);
}
__device__ __forceinline__ u32 saddr(const void* p) {
    return (u32)__cvta_generic_to_shared(p);
}
__device__ __forceinline__ void lds2d(u64& a, u64& b, u32 addr) {
    asm volatile("ld.shared.v2.b64 {%0, %1}, [%2];" : "=l"(a), "=l"(b) : "r"(addr));
}
__device__ __forceinline__ void sts64d(u32 addr, u64 v) {
    asm volatile("st.shared.b64 [%0], %1;" :: "r"(addr), "l"(v));
}
__device__ __forceinline__ void ldg2(u64& a, u64& b, const void* p) {
    asm volatile("ld.global.v2.b64 {%0, %1}, [%2];" : "=l"(a), "=l"(b) : "l"(p));
}
__device__ __forceinline__ void ldg1(u64& a, const void* p) {
    asm volatile("ld.global.b64 %0, [%1];" : "=l"(a) : "l"(p));
}
__device__ __forceinline__ float2 h2f(u32 v) {
    __half2 h = *reinterpret_cast<__half2*>(&v);
    return __half22float2(h);
}

// ============ Kernel 0: fuse Wc = Wih@Wemb, bc once ============
__global__ void prep_kernel(const float* __restrict__ Wemb, const float* __restrict__ bemb,
                            const float* __restrict__ Wih,  const float* __restrict__ bih,
                            const float* __restrict__ bhh)
{
    const int tid = threadIdx.x;
    for (int i = tid; i < 480; i += blockDim.x) {
        const int g = i / 120, rem = i - g * 120;
        const int k = rem / 6, jj = rem - k * 6;
        const int r = g * H_DIM + k;
        float c0 = 0.f, c1 = 0.f;
#pragma unroll
        for (int e = 0; e < E_DIM; ++e) {
            const float wie = Wih[r * E_DIM + e];
            c0 += wie * Wemb[e * IN_DIM + 2 * jj];
            c1 += wie * Wemb[e * IN_DIM + 2 * jj + 1];
        }
        g_wcx[g][k][jj] = pack2(c0, c1);
    }
    if (tid < H_DIM) {
        float4 b4;
        float* bp = &b4.x;
#pragma unroll
        for (int g = 0; g < 4; ++g) {
            const int r = g * H_DIM + tid;
            float b = bih[r] + bhh[r];
#pragma unroll
            for (int e = 0; e < E_DIM; ++e) b += Wih[r * E_DIM + e] * bemb[e];
            bp[g] = b;
        }
        g_bc4[tid] = b4;
    }
}

// ============ Fused kernel: per-warp xgate phase + recurrence phase ============
// warp = batch row. No cross-block dependency: phase 2 reads only scratch
// written by this same warp in phase 1.
__global__ void __launch_bounds__(32, 14)
fused_kernel(const float* __restrict__ X,
             const float* __restrict__ Whh,
             const float* __restrict__ Wout, const float* __restrict__ bout,
             float* __restrict__ out)
{
    __shared__ __align__(16) u64 hdup[2][H_DIM];   // (h,h) pairs, ping-pong

    const int lane = threadIdx.x;
    const int grow = blockIdx.x;
    const bool hL = lane < H_DIM;
    const bool oL = (lane >= H_DIM) && (lane < H_DIM + 3);
    const int k   = hL ? lane : 0;

    // ======== Phase 1: x-gates for this row -> fp16 scratch ========
    {
        u64 wg[4][6];
#pragma unroll
        for (int g = 0; g < 4; ++g) {
            ldg2(wg[g][0], wg[g][1], &g_wcx[g][k][0]);
            ldg2(wg[g][2], wg[g][3], &g_wcx[g][k][2]);
            ldg2(wg[g][4], wg[g][5], &g_wcx[g][k][4]);
        }
        const float4 b4 = g_bc4[k];

        const float* xp = X + (long long)grow * IN_DIM;
        u64* op = g_xg + (size_t)grow * TPAD * H_DIM + k;

        // 4-deep register ring of x (6 u64 per timestep)
        u64 xr[4][6];
#pragma unroll
        for (int p = 0; p < 4; ++p) {
            ldg2(xr[p][0], xr[p][1], xp);
            ldg2(xr[p][2], xr[p][3], xp + 4);
            ldg2(xr[p][4], xr[p][5], xp + 8);
            xp += XS;
        }

#pragma unroll 4
        for (int it = 0; it < T_STEPS; ++it) {
            const int sl = it & 3;
            u64 a0 = pack2(b4.x, 0.f), a1 = pack2(b4.y, 0.f);
            u64 a2 = pack2(b4.z, 0.f), a3 = pack2(b4.w, 0.f);
#pragma unroll
            for (int j = 0; j < 6; ++j) {
                const u64 xv = xr[sl][j];
                fma2(a0, wg[0][j], xv); fma2(a1, wg[1][j], xv);
                fma2(a2, wg[2][j], xv); fma2(a3, wg[3][j], xv);
            }
            if (it + 4 < T_STEPS) {
                ldg2(xr[sl][0], xr[sl][1], xp);
                ldg2(xr[sl][2], xr[sl][3], xp + 4);
                ldg2(xr[sl][4], xr[sl][5], xp + 8);
                xp += XS;
            }
            __half2 hl = __floats2half2_rn(hsum2(a0), hsum2(a1));
            __half2 hh = __floats2half2_rn(hsum2(a2), hsum2(a3));
            const u64 v = pack2u(*reinterpret_cast<u32*>(&hl),
                                 *reinterpret_cast<u32*>(&hh));
            if (lane < H_DIM) *op = v;
            op += H_DIM;
        }
    }

    // ======== Phase 2: recurrence ========
    u64 w01[H_DIM], w23[H_DIM];
    u64 bO = 0ull;
    if (hL) {
#pragma unroll
        for (int j = 0; j < H_DIM; ++j) {
            w01[j] = pack2(Whh[lane * H_DIM + j],               Whh[(H_DIM + lane) * H_DIM + j]);
            w23[j] = pack2(Whh[(2 * H_DIM + lane) * H_DIM + j], Whh[(3 * H_DIM + lane) * H_DIM + j]);
        }
    } else {
#pragma unroll
        for (int j = 0; j < H_DIM; ++j) { w01[j] = 0ull; w23[j] = 0ull; }
        if (oL) {
            const int m = lane - H_DIM;
#pragma unroll
            for (int j = 0; j < H_DIM; ++j) w01[j] = pack2(Wout[m * H_DIM + j], 0.f);
            bO = pack2(bout[m], 0.f);
        }
    }
    if (hL) hdup[0][lane] = 0ull;
    __syncwarp();

    const u32 h0a = saddr(&hdup[0][0]);
    const u32 h1a = saddr(&hdup[1][0]);
    const u32 hw0 = h0a + lane * 8;
    const u32 hw1 = h1a + lane * 8;

    const u64* gp = g_xg + (size_t)grow * TPAD * H_DIM + k;
    u64 pa, pb, pc, pd;
    ldg1(pa, gp);
    ldg1(pb, gp + H_DIM);
    ldg1(pc, gp + 2 * H_DIM);
    ldg1(pd, gp + 3 * H_DIM);
    gp += 4 * H_DIM;

    float c = 0.f;
    float* outp = out + (long long)grow * 3 + (lane - H_DIM) - OS;

#define STEP(PX, HRD, HWR, DOOUT)                                              \
    do {                                                                       \
        u32 xl, xh; unpack2u(xl, xh, (PX));                                    \
        const float2 flo = h2f(xl);                                            \
        const float2 fhi = h2f(xh);                                            \
        u64 a01 = hL ? pack2(flo.x, flo.y) : bO;                               \
        u64 a23 = pack2(fhi.x, fhi.y);                                         \
        u64 a01b = 0ull, a23b = 0ull;                                          \
        u64 e0, e1, e2, e3;                                                    \
        lds2d(e0, e1, (HRD));        lds2d(e2, e3, (HRD) + 16);                \
        fma2(a01, w01[0], e0); fma2(a23, w23[0], e0);                          \
        fma2(a01, w01[1], e1); fma2(a23, w23[1], e1);                          \
        fma2(a01, w01[2], e2); fma2(a23, w23[2], e2);                          \
        fma2(a01, w01[3], e3); fma2(a23, w23[3], e3);                          \
        lds2d(e0, e1, (HRD) + 32);   lds2d(e2, e3, (HRD) + 48);                \
        fma2(a01, w01[4], e0); fma2(a23, w23[4], e0);                          \
        fma2(a01, w01[5], e1); fma2(a23, w23[5], e1);                          \
        fma2(a01, w01[6], e2); fma2(a23, w23[6], e2);                          \
        fma2(a01, w01[7], e3); fma2(a23, w23[7], e3);                          \
        lds2d(e0, e1, (HRD) + 64);   lds2d(e2, e3, (HRD) + 80);                \
        fma2(a01, w01[8],  e0); fma2(a23, w23[8],  e0);                        \
        fma2(a01, w01[9],  e1); fma2(a23, w23[9],  e1);                        \
        fma2(a01b, w01[10], e2); fma2(a23b, w23[10], e2);                      \
        fma2(a01b, w01[11], e3); fma2(a23b, w23[11], e3);                      \
        lds2d(e0, e1, (HRD) + 96);   lds2d(e2, e3, (HRD) + 112);               \
        fma2(a01b, w01[12], e0); fma2(a23b, w23[12], e0);                      \
        fma2(a01b, w01[13], e1); fma2(a23b, w23[13], e1);                      \
        fma2(a01b, w01[14], e2); fma2(a23b, w23[14], e2);                      \
        fma2(a01b, w01[15], e3); fma2(a23b, w23[15], e3);                      \
        lds2d(e0, e1, (HRD) + 128);  lds2d(e2, e3, (HRD) + 144);               \
        fma2(a01b, w01[16], e0); fma2(a23b, w23[16], e0);                      \
        fma2(a01b, w01[17], e1); fma2(a23b, w23[17], e1);                      \
        fma2(a01b, w01[18], e2); fma2(a23b, w23[18], e2);                      \
        fma2(a01b, w01[19], e3); fma2(a23b, w23[19], e3);                      \
        asm("add.rn.f32x2 %0, %0, %1;" : "+l"(a01) : "l"(a01b));               \
        asm("add.rn.f32x2 %0, %0, %1;" : "+l"(a23) : "l"(a23b));               \
        float p0, p1, p2, p3;                                                  \
        unpack2(p0, p1, a01); unpack2(p2, p3, a23);                            \
        const float iv = sig_a(p0), fv = sig_a(p1);                            \
        const float gv = tanh_a(p2), ov = sig_a(p3);                           \
        c = fmaf(fv, c, iv * gv);                                              \
        const float h = ov * tanh_a(c);                                        \
        if (hL) sts64d((HWR), pack2(h, h));                                    \
        if (oL && (DOOUT)) *outp = p0;                                         \
        outp += OS;                                                            \
        ldg1((PX), gp); gp += H_DIM;                                           \
        __syncwarp();                                                          \
    } while (0)

    STEP(pa, h0a, hw1, false);
    STEP(pb, h1a, hw0, true);
    STEP(pc, h0a, hw1, true);
    STEP(pd, h1a, hw0, true);
#pragma unroll 1
    for (int t4 = 4; t4 < T_STEPS; t4 += 4) {
        STEP(pa, h0a, hw1, true);
        STEP(pb, h1a, hw0, true);
        STEP(pc, h0a, hw1, true);
        STEP(pd, h1a, hw0, true);
    }
#undef STEP

    // final out[T-1] from h_511 (in buf 0)
    {
        u64 a01 = bO;
        u64 e0, e1, e2, e3;
#pragma unroll
        for (int q = 0; q < 5; ++q) {
            lds2d(e0, e1, h0a + q * 32);
            lds2d(e2, e3, h0a + q * 32 + 16);
            fma2(a01, w01[4 * q],     e0); fma2(a01, w01[4 * q + 1], e1);
            fma2(a01, w01[4 * q + 2], e2); fma2(a01, w01[4 * q + 3], e3);
        }
        if (oL) {
            float v, d; unpack2(v, d, a01);
            *outp = v;
        }
    }
}

extern "C" void kernel_launch(void* const* d_in, const int* in_sizes, int n_in,
                              void* d_out, int out_size) {
    const float* X    = (const float*)d_in[0];
    const float* Wemb = (const float*)d_in[1];
    const float* bemb = (const float*)d_in[2];
    const float* Wih  = (const float*)d_in[3];
    const float* bih  = (const float*)d_in[4];
    const float* Whh  = (const float*)d_in[5];
    const float* bhh  = (const float*)d_in[6];
    const float* Wout = (const float*)d_in[7];
    const float* bout = (const float*)d_in[8];
    float* out = (float*)d_out;

    prep_kernel<<<1, 256>>>(Wemb, bemb, Wih, bih, bhh);
    fused_kernel<<<BATCH, 32>>>(X, Whh, Wout, bout, out);
}

// round 17
// speedup vs baseline: 1.2558x; 1.2558x over previous
#include <cuda_runtime.h>
#include <cuda_fp16.h>
#include <cstdint>

#define T_STEPS 512
#define BATCH   2048
#define IN_DIM  12
#define E_DIM   15
#define H_DIM   20
#define XS      (BATCH * IN_DIM)
#define OS      (BATCH * 3)
#define TPAD    (T_STEPS + 4)         // prefetch pad
#define TROWS   16                    // batch rows per mma tile
#define TCH     32                    // timesteps per xgate block

typedef unsigned long long u64;
typedef uint32_t u32;

// Scratch: x-gate pre-activations as half4 (i,f,g,o) = one u64 per (b,t,cell).
__device__ __align__(16) u64    g_xg[(size_t)BATCH * TPAD * H_DIM];
// Precomputed per-lane B fragments (10 n-tiles) and per-(nt,tid) bias pairs.
__device__ __align__(16) u64    g_bfrag[10][32];
__device__ __align__(16) float2 g_biasf[10][4];

__device__ __forceinline__ u64 pack2(float x, float y) {
    u64 u; asm("mov.b64 %0, {%1, %2};" : "=l"(u) : "f"(x), "f"(y)); return u;
}
__device__ __forceinline__ void unpack2(float& x, float& y, u64 u) {
    asm("mov.b64 {%0, %1}, %2;" : "=f"(x), "=f"(y) : "l"(u));
}
__device__ __forceinline__ u64 pack2u(u32 lo, u32 hi) {
    u64 u; asm("mov.b64 %0, {%1, %2};" : "=l"(u) : "r"(lo), "r"(hi)); return u;
}
__device__ __forceinline__ void unpack2u(u32& lo, u32& hi, u64 u) {
    asm("mov.b64 {%0, %1}, %2;" : "=r"(lo), "=r"(hi) : "l"(u));
}
__device__ __forceinline__ void fma2(u64& d, u64 a, u64 b) {
    asm("fma.rn.f32x2 %0, %1, %2, %0;" : "+l"(d) : "l"(a), "l"(b));
}
__device__ __forceinline__ float tanh_a(float x) {
    float y; asm("tanh.approx.f32 %0, %1;" : "=f"(y) : "f"(x)); return y;
}
__device__ __forceinline__ float sig_a(float x) {
    return fmaf(0.5f, tanh_a(0.5f * x), 0.5f);
}
__device__ __forceinline__ u32 saddr(const void* p) {
    return (u32)__cvta_generic_to_shared(p);
}
__device__ __forceinline__ void lds2d(u64& a, u64& b, u32 addr) {
    asm volatile("ld.shared.v2.b64 {%0, %1}, [%2];" : "=l"(a), "=l"(b) : "r"(addr));
}
__device__ __forceinline__ void sts64d(u32 addr, u64 v) {
    asm volatile("st.shared.b64 [%0], %1;" :: "r"(addr), "l"(v));
}
__device__ __forceinline__ void ldg1(u64& a, const void* p) {
    asm volatile("ld.global.b64 %0, [%1];" : "=l"(a) : "l"(p));
}
__device__ __forceinline__ float2 h2f(u32 v) {
    __half2 h = *reinterpret_cast<__half2*>(&v);
    return __half22float2(h);
}

// ============ Kernel 0: fused weights -> mma B fragments + biases ============
__global__ void prep_kernel(const float* __restrict__ Wemb, const float* __restrict__ bemb,
                            const float* __restrict__ Wih,  const float* __restrict__ bih,
                            const float* __restrict__ bhh)
{
    __shared__ float wcs[80][12];
    __shared__ float bcs[80];
    const int tid = threadIdx.x;

    for (int i = tid; i < 960; i += blockDim.x) {
        const int r = i / 12, j = i - r * 12;
        float s = 0.f;
#pragma unroll
        for (int e = 0; e < E_DIM; ++e)
            s += Wih[r * E_DIM + e] * Wemb[e * IN_DIM + j];
        wcs[r][j] = s;
    }
    for (int r = tid; r < 80; r += blockDim.x) {
        float b = bih[r] + bhh[r];
#pragma unroll
        for (int e = 0; e < E_DIM; ++e) b += Wih[r * E_DIM + e] * bemb[e];
        bcs[r] = b;
    }
    __syncthreads();

    // B fragment (m16n8k16, col-major B = Wc^T, K=16 with cols 12-15 zero):
    // lane l: q = l/4, td = l%4. b0 = {B[2td][q], B[2td+1][q]},
    // b1 = {B[2td+8][q], B[2td+9][q]}; B[kk][n] = Wc[nt*8+n][kk], 0 for kk>=12.
    for (int i = tid; i < 320; i += blockDim.x) {
        const int nt = i >> 5, l = i & 31;
        const int q = l >> 2, td = l & 3;
        const int gate = nt * 8 + q;
        __half2 b0 = __floats2half2_rn(wcs[gate][2 * td], wcs[gate][2 * td + 1]);
        const int k1 = 2 * td + 8;
        float f0 = (k1 < 12)     ? wcs[gate][k1]     : 0.f;
        float f1 = (k1 + 1 < 12) ? wcs[gate][k1 + 1] : 0.f;
        __half2 b1 = __floats2half2_rn(f0, f1);
        g_bfrag[nt][l] = pack2u(*reinterpret_cast<u32*>(&b0),
                                *reinterpret_cast<u32*>(&b1));
    }
    // bias pairs: D cols = 2*td, 2*td+1 -> gates nt*8+2td(+1)
    for (int i = tid; i < 40; i += blockDim.x) {
        const int nt = i >> 2, td = i & 3;
        g_biasf[nt][td] = make_float2(bcs[nt * 8 + 2 * td], bcs[nt * 8 + 2 * td + 1]);
    }
}

// ============ Kernel 1: x-gate precompute via HMMA ============
// warp = (16 batch rows, 32 timesteps). Per t: one m16n8k16 A-tile (x, fp16,
// K padded 12->16) x 10 B-tiles (80 gates), epilogue transposed to the same
// [b][t][cell] half4 layout the lstm kernel already consumes.
__global__ void __launch_bounds__(32, 16)
xgate_kernel(const float* __restrict__ X)
{
    __shared__ __align__(16) __half xtile[2][TROWS][16];   // 2 x 512B, cols 12-15 zero
    __shared__ __align__(16) __half dtile[TROWS][84];      // 168B rows (pad 4)

    const int lane = threadIdx.x;
    const int b0   = blockIdx.x * TROWS;
    const int t0   = blockIdx.y * TCH;
    const int g    = lane >> 2;
    const int tid4 = lane & 3;

    // register-resident B fragments + biases
    u64 bfrag[10];
    float2 bias[10];
#pragma unroll
    for (int nt = 0; nt < 10; ++nt) {
        ldg1(bfrag[nt], &g_bfrag[nt][lane]);
        bias[nt] = g_biasf[nt][tid4];
    }

    // zero pad cols 12-15 of both x tiles (never rewritten)
    if (lane < TROWS) {
        *reinterpret_cast<u64*>(&xtile[0][lane][12]) = 0ull;
        *reinterpret_cast<u64*>(&xtile[1][lane][12]) = 0ull;
    }

    // staging: 96 float-pairs per tile, 3 per lane
    int srow[3], scp[3];
#pragma unroll
    for (int i = 0; i < 3; ++i) {
        const int p = lane + 32 * i;
        srow[i] = p / 6; scp[i] = p - srow[i] * 6;
    }

    // transpose-pass index tables (10 per lane)
    u32 t_doff[10];   // dtile byte offset: r*168 + cell*2
    u32 t_goff[10];   // global u64-index offset: r*TPAD*20 + cell
#pragma unroll
    for (int q = 0; q < 10; ++q) {
        const int idx = lane + 32 * q;          // 0..319
        const int r = idx / 20, cell = idx - r * 20;
        t_doff[q] = (u32)(r * 168 + cell * 2);
        t_goff[q] = (u32)(r * TPAD * H_DIM + cell);
    }

    // 4-deep x ring (float2 x 3 per slot)
    float2 ring[4][3];
#pragma unroll
    for (int s = 0; s < 4; ++s)
#pragma unroll
        for (int i = 0; i < 3; ++i)
            ring[s][i] = *reinterpret_cast<const float2*>(
                X + ((size_t)(t0 + s) * BATCH + b0 + srow[i]) * IN_DIM + scp[i] * 2);

    // stage t0 into xtile[0]
#pragma unroll
    for (int i = 0; i < 3; ++i)
        *reinterpret_cast<__half2*>(&xtile[0][srow[i]][scp[i] * 2]) =
            __floats2half2_rn(ring[0][i].x, ring[0][i].y);
    __syncwarp();

    const u32 xb    = saddr(&xtile[0][0][0]);
    const u32 db    = saddr(&dtile[0][0]);
    const u32 abase = xb + g * 32 + tid4 * 4;

#pragma unroll 4
    for (int tl = 0; tl < TCH; ++tl) {
        const int t = t0 + tl;

        // A fragment: a0={A[g][2td..]}, a1=rows+8, a2=cols+8, a3=both+8
        const u32 xa = abase + (tl & 1) * 512;
        u32 a0, a1, a2, a3;
        asm volatile("ld.shared.b32 %0, [%1];" : "=r"(a0) : "r"(xa));
        asm volatile("ld.shared.b32 %0, [%1];" : "=r"(a1) : "r"(xa + 256));
        asm volatile("ld.shared.b32 %0, [%1];" : "=r"(a2) : "r"(xa + 16));
        asm volatile("ld.shared.b32 %0, [%1];" : "=r"(a3) : "r"(xa + 272));

#pragma unroll
        for (int nt = 0; nt < 10; ++nt) {
            float c0 = bias[nt].x, c1 = bias[nt].y;
            float c2 = bias[nt].x, c3 = bias[nt].y;
            u32 blo, bhi; unpack2u(blo, bhi, bfrag[nt]);
            asm volatile(
                "mma.sync.aligned.m16n8k16.row.col.f32.f16.f16.f32 "
                "{%0,%1,%2,%3}, {%4,%5,%6,%7}, {%8,%9}, {%0,%1,%2,%3};"
                : "+f"(c0), "+f"(c1), "+f"(c2), "+f"(c3)
                : "r"(a0), "r"(a1), "r"(a2), "r"(a3), "r"(blo), "r"(bhi));
            __half2 h01 = __floats2half2_rn(c0, c1);
            __half2 h23 = __floats2half2_rn(c2, c3);
            const u32 doff = db + nt * 16 + tid4 * 4;
            asm volatile("st.shared.b32 [%0], %1;"
                         :: "r"(doff + g * 168), "r"(*reinterpret_cast<u32*>(&h01)));
            asm volatile("st.shared.b32 [%0], %1;"
                         :: "r"(doff + (g + 8) * 168), "r"(*reinterpret_cast<u32*>(&h23)));
        }
        __syncwarp();

        // transpose dtile[r][gate] -> g_xg[(b0+r)][t][cell] half4 (i,f,g,o)
        {
            u64* gbase = g_xg + ((size_t)b0 * TPAD + t) * H_DIM;
#pragma unroll
            for (int q = 0; q < 10; ++q) {
                u32 v0, v1, v2, v3;
                const u32 da = db + t_doff[q];
                asm volatile("ld.shared.u16 %0, [%1];" : "=r"(v0) : "r"(da));
                asm volatile("ld.shared.u16 %0, [%1];" : "=r"(v1) : "r"(da + 40));
                asm volatile("ld.shared.u16 %0, [%1];" : "=r"(v2) : "r"(da + 80));
                asm volatile("ld.shared.u16 %0, [%1];" : "=r"(v3) : "r"(da + 120));
                gbase[t_goff[q]] = pack2u(v0 | (v1 << 16), v2 | (v3 << 16));
            }
        }

        // stage t+1 (from ring), prefetch t+4 into freed slot
        if (tl + 1 < TCH) {
            const int sl = (tl + 1) & 3;
#pragma unroll
            for (int i = 0; i < 3; ++i)
                *reinterpret_cast<__half2*>(&xtile[(tl + 1) & 1][srow[i]][scp[i] * 2]) =
                    __floats2half2_rn(ring[sl][i].x, ring[sl][i].y);
        }
        if (tl + 4 < TCH) {
            const int sl4 = tl & 3;
#pragma unroll
            for (int i = 0; i < 3; ++i)
                ring[sl4][i] = *reinterpret_cast<const float2*>(
                    X + ((size_t)(t0 + tl + 4) * BATCH + b0 + srow[i]) * IN_DIM + scp[i] * 2);
        }
        __syncwarp();
    }
}

// ============ Kernel 2: recurrence (R15 form, unchanged) ============
__global__ void __launch_bounds__(32, 14)
lstm_kernel(const float* __restrict__ Whh,
            const float* __restrict__ Wout, const float* __restrict__ bout,
            float* __restrict__ out)
{
    __shared__ __align__(16) u64 hdup[2][H_DIM];   // (h,h) pairs, ping-pong

    const int lane = threadIdx.x;
    const int grow = blockIdx.x;
    const bool hL = lane < H_DIM;
    const bool oL = (lane >= H_DIM) && (lane < H_DIM + 3);
    const int k   = hL ? lane : 0;

    u64 w01[H_DIM], w23[H_DIM];
    u64 bO = 0ull;
    if (hL) {
#pragma unroll
        for (int j = 0; j < H_DIM; ++j) {
            w01[j] = pack2(Whh[lane * H_DIM + j],               Whh[(H_DIM + lane) * H_DIM + j]);
            w23[j] = pack2(Whh[(2 * H_DIM + lane) * H_DIM + j], Whh[(3 * H_DIM + lane) * H_DIM + j]);
        }
    } else {
#pragma unroll
        for (int j = 0; j < H_DIM; ++j) { w01[j] = 0ull; w23[j] = 0ull; }
        if (oL) {
            const int m = lane - H_DIM;
#pragma unroll
            for (int j = 0; j < H_DIM; ++j) w01[j] = pack2(Wout[m * H_DIM + j], 0.f);
            bO = pack2(bout[m], 0.f);
        }
    }
    if (hL) hdup[0][lane] = 0ull;
    __syncwarp();

    const u32 h0a = saddr(&hdup[0][0]);
    const u32 h1a = saddr(&hdup[1][0]);
    const u32 hw0 = h0a + lane * 8;
    const u32 hw1 = h1a + lane * 8;

    const u64* gp = g_xg + (size_t)grow * TPAD * H_DIM + k;
    u64 pa, pb, pc, pd;
    ldg1(pa, gp);
    ldg1(pb, gp + H_DIM);
    ldg1(pc, gp + 2 * H_DIM);
    ldg1(pd, gp + 3 * H_DIM);
    gp += 4 * H_DIM;

    float c = 0.f;
    float* outp = out + (long long)grow * 3 + (lane - H_DIM) - OS;

#define STEP(PX, HRD, HWR, DOOUT)                                              \
    do {                                                                       \
        u32 xl, xh; unpack2u(xl, xh, (PX));                                    \
        const float2 flo = h2f(xl);                                            \
        const float2 fhi = h2f(xh);                                            \
        u64 a01 = hL ? pack2(flo.x, flo.y) : bO;                               \
        u64 a23 = pack2(fhi.x, fhi.y);                                         \
        u64 a01b = 0ull, a23b = 0ull;                                          \
        u64 e0, e1, e2, e3;                                                    \
        lds2d(e0, e1, (HRD));        lds2d(e2, e3, (HRD) + 16);                \
        fma2(a01, w01[0], e0); fma2(a23, w23[0], e0);                          \
        fma2(a01, w01[1], e1); fma2(a23, w23[1], e1);                          \
        fma2(a01, w01[2], e2); fma2(a23, w23[2], e2);                          \
        fma2(a01, w01[3], e3); fma2(a23, w23[3], e3);                          \
        lds2d(e0, e1, (HRD) + 32);   lds2d(e2, e3, (HRD) + 48);                \
        fma2(a01, w01[4], e0); fma2(a23, w23[4], e0);                          \
        fma2(a01, w01[5], e1); fma2(a23, w23[5], e1);                          \
        fma2(a01, w01[6], e2); fma2(a23, w23[6], e2);                          \
        fma2(a01, w01[7], e3); fma2(a23, w23[7], e3);                          \
        lds2d(e0, e1, (HRD) + 64);   lds2d(e2, e3, (HRD) + 80);                \
        fma2(a01, w01[8],  e0); fma2(a23, w23[8],  e0);                        \
        fma2(a01, w01[9],  e1); fma2(a23, w23[9],  e1);                        \
        fma2(a01b, w01[10], e2); fma2(a23b, w23[10], e2);                      \
        fma2(a01b, w01[11], e3); fma2(a23b, w23[11], e3);                      \
        lds2d(e0, e1, (HRD) + 96);   lds2d(e2, e3, (HRD) + 112);               \
        fma2(a01b, w01[12], e0); fma2(a23b, w23[12], e0);                      \
        fma2(a01b, w01[13], e1); fma2(a23b, w23[13], e1);                      \
        fma2(a01b, w01[14], e2); fma2(a23b, w23[14], e2);                      \
        fma2(a01b, w01[15], e3); fma2(a23b, w23[15], e3);                      \
        lds2d(e0, e1, (HRD) + 128);  lds2d(e2, e3, (HRD) + 144);               \
        fma2(a01b, w01[16], e0); fma2(a23b, w23[16], e0);                      \
        fma2(a01b, w01[17], e1); fma2(a23b, w23[17], e1);                      \
        fma2(a01b, w01[18], e2); fma2(a23b, w23[18], e2);                      \
        fma2(a01b, w01[19], e3); fma2(a23b, w23[19], e3);                      \
        asm("add.rn.f32x2 %0, %0, %1;" : "+l"(a01) : "l"(a01b));               \
        asm("add.rn.f32x2 %0, %0, %1;" : "+l"(a23) : "l"(a23b));               \
        float p0, p1, p2, p3;                                                  \
        unpack2(p0, p1, a01); unpack2(p2, p3, a23);                            \
        const float iv = sig_a(p0), fv = sig_a(p1);                            \
        const float gv = tanh_a(p2), ov = sig_a(p3);                           \
        c = fmaf(fv, c, iv * gv);                                              \
        const float h = ov * tanh_a(c);                                        \
        if (hL) sts64d((HWR), pack2(h, h));                                    \
        if (oL && (DOOUT)) *outp = p0;                                         \
        outp += OS;                                                            \
        ldg1((PX), gp); gp += H_DIM;                                           \
        __syncwarp();                                                          \
    } while (0)

    STEP(pa, h0a, hw1, false);
    STEP(pb, h1a, hw0, true);
    STEP(pc, h0a, hw1, true);
    STEP(pd, h1a, hw0, true);
#pragma unroll 1
    for (int t4 = 4; t4 < T_STEPS; t4 += 4) {
        STEP(pa, h0a, hw1, true);
        STEP(pb, h1a, hw0, true);
        STEP(pc, h0a, hw1, true);
        STEP(pd, h1a, hw0, true);
    }
#undef STEP

    // final out[T-1] from h_511 (in buf 0)
    {
        u64 a01 = bO;
        u64 e0, e1, e2, e3;
#pragma unroll
        for (int q = 0; q < 5; ++q) {
            lds2d(e0, e1, h0a + q * 32);
            lds2d(e2, e3, h0a + q * 32 + 16);
            fma2(a01, w01[4 * q],     e0); fma2(a01, w01[4 * q + 1], e1);
            fma2(a01, w01[4 * q + 2], e2); fma2(a01, w01[4 * q + 3], e3);
        }
        if (oL) {
            float v, d; unpack2(v, d, a01);
            *outp = v;
        }
    }
}

extern "C" void kernel_launch(void* const* d_in, const int* in_sizes, int n_in,
                              void* d_out, int out_size) {
    const float* X    = (const float*)d_in[0];
    const float* Wemb = (const float*)d_in[1];
    const float* bemb = (const float*)d_in[2];
    const float* Wih  = (const float*)d_in[3];
    const float* bih  = (const float*)d_in[4];
    const float* Whh  = (const float*)d_in[5];
    const float* bhh  = (const float*)d_in[6];
    const float* Wout = (const float*)d_in[7];
    const float* bout = (const float*)d_in[8];
    float* out = (float*)d_out;

    prep_kernel<<<1, 256>>>(Wemb, bemb, Wih, bih, bhh);
    dim3 gx(BATCH / TROWS, T_STEPS / TCH);   // (128, 16)
    xgate_kernel<<<gx, 32>>>(X);
    lstm_kernel<<<BATCH, 32>>>(Whh, Wout, bout, out);
}